// round 5
// baseline (speedup 1.0000x reference)
#include <cuda_runtime.h>

#define BSZ 2
#define SEQ 4096
#define DIM 1024
#define DIM4 (DIM / 4)         // 256 float4 per row
#define CHUNK 32
#define NCHUNK (SEQ / CHUNK)   // 128

// ---- scratch (__device__ globals) ----
__device__ int   g_pos[BSZ * SEQ];
__device__ float g_pk [BSZ * SEQ];
__device__ float g_Pc [BSZ * NCHUNK];
__device__ int   g_nb [BSZ];
__device__ float4 g_E4[BSZ * NCHUNK * DIM4];  // chunk-end local states
__device__ float4 g_S4[BSZ * NCHUNK * DIM4];  // incoming state per chunk

// ---------------------------------------------------------------------------
// Kernel 1: mask scan -> pos/pk/nb + per-chunk decay products (warp-reduced).
// One block per batch, 1024 threads.
// ---------------------------------------------------------------------------
__global__ void prep_kernel(const float* __restrict__ prob,
                            const void* __restrict__ mask_raw) {
    const int b = blockIdx.x;
    const int t = threadIdx.x;

    __shared__ int   s_w;
    __shared__ int   s_wsum[32];
    __shared__ int   s_total;
    __shared__ float s_pk[SEQ];     // compacted clipped p (16 KB)

    // ---- detect mask element width (1-byte bool vs 4-byte 0/1) ----
    if (t == 0) s_w = 0;
    __syncthreads();
    {
        const unsigned char* mb = (const unsigned char*)mask_raw;
        int f = 0;
        for (int j = t; j < (BSZ * SEQ) / 4; j += blockDim.x)
            f |= mb[4 * j + 1];
        if (f) s_w = 1;
    }
    __syncthreads();
    const int onebyte = s_w;

    const int base = t * 4;
    int m[4];
    if (onebyte) {
        const unsigned char* mb = (const unsigned char*)mask_raw + b * SEQ;
        #pragma unroll
        for (int j = 0; j < 4; j++) m[j] = mb[base + j] ? 1 : 0;
    } else {
        const int* mi = (const int*)mask_raw + b * SEQ;
        #pragma unroll
        for (int j = 0; j < 4; j++) m[j] = mi[base + j] ? 1 : 0;
    }
    int cnt = m[0] + m[1] + m[2] + m[3];

    // ---- block inclusive scan of per-thread counts ----
    int v = cnt;
    const int lane = t & 31, wid = t >> 5;
    #pragma unroll
    for (int o = 1; o < 32; o <<= 1) {
        int u = __shfl_up_sync(0xffffffffu, v, o);
        if (lane >= o) v += u;
    }
    if (lane == 31) s_wsum[wid] = v;
    __syncthreads();
    if (wid == 0) {
        int w = s_wsum[lane];
        #pragma unroll
        for (int o = 1; o < 32; o <<= 1) {
            int u = __shfl_up_sync(0xffffffffu, w, o);
            if (lane >= o) w += u;
        }
        s_wsum[lane] = w;
        if (lane == 31) s_total = w;
    }
    __syncthreads();

    int run = v - cnt + (wid ? s_wsum[wid - 1] : 0);
    const int nb = s_total;
    if (t == 0) g_nb[b] = nb;

    const float* pb = prob + b * SEQ;
    #pragma unroll
    for (int j = 0; j < 4; j++) {
        const int l = base + j;
        if (m[j]) {
            float p = pb[l];
            p = fminf(fmaxf(p, 1e-4f), 0.9999f);
            g_pos[b * SEQ + run] = l;
            g_pk [b * SEQ + run] = p;
            s_pk[run] = p;
            run++;
        }
    }
    __syncthreads();

    // ---- per-chunk decay products: one warp per chunk, shuffle-reduce ----
    const int nc = (nb + CHUNK - 1) / CHUNK;
    for (int c = wid; c < nc; c += 32) {
        const int k = c * CHUNK + lane;
        float a = (k < nb) ? (1.f - s_pk[k]) : 1.f;
        #pragma unroll
        for (int o = 16; o > 0; o >>= 1)
            a *= __shfl_xor_sync(0xffffffffu, a, o);
        if (lane == 0) g_Pc[b * NCHUNK + c] = a;
    }
}

// ---------------------------------------------------------------------------
// Kernel 2: chunk-local scans from zero -> chunk-end states g_E4 (float4).
// grid (2, NCHUNK, BSZ), 128 threads: d4 = blockIdx.x*128 + t covers DIM4.
// ---------------------------------------------------------------------------
__global__ void escan_kernel(const float* __restrict__ hidden) {
    const int b = blockIdx.z, c = blockIdx.y;
    const int d4 = blockIdx.x * 128 + threadIdx.x;
    const int nb = g_nb[b];
    const int k0 = c * CHUNK;
    if (k0 >= nb) return;
    const int n = min(CHUNK, nb - k0);

    __shared__ int   spos[CHUNK];
    __shared__ float spk [CHUNK];
    if (threadIdx.x < n) {
        spos[threadIdx.x] = g_pos[b * SEQ + k0 + threadIdx.x];
        spk [threadIdx.x] = g_pk [b * SEQ + k0 + threadIdx.x];
    }
    __syncthreads();

    const float4* hb = (const float4*)hidden + (size_t)b * SEQ * DIM4 + d4;
    float4 s = make_float4(0.f, 0.f, 0.f, 0.f);

    #pragma unroll
    for (int j0 = 0; j0 < CHUNK; j0 += 8) {
        float4 h[8];
        #pragma unroll
        for (int jj = 0; jj < 8; jj++) {
            const int j = j0 + jj;
            h[jj] = (j < n) ? __ldg(hb + (size_t)spos[j] * DIM4)
                            : make_float4(0.f, 0.f, 0.f, 0.f);
        }
        #pragma unroll
        for (int jj = 0; jj < 8; jj++) {
            const int j = j0 + jj;
            if (j < n) {
                const float p = spk[j], a = 1.f - p;
                s.x = fmaf(a, s.x, p * h[jj].x);
                s.y = fmaf(a, s.y, p * h[jj].y);
                s.z = fmaf(a, s.z, p * h[jj].z);
                s.w = fmaf(a, s.w, p * h[jj].w);
            }
        }
    }
    g_E4[(size_t)(b * NCHUNK + c) * DIM4 + d4] = s;
}

// ---------------------------------------------------------------------------
// Kernel 3: serial combine across chunks per channel (float4) -> g_S4.
// grid (2, BSZ), 256 threads: d4 = blockIdx.x*256 + t covers DIM4... (2*256=512>256)
// Use grid (1, BSZ) with 256 threads covering DIM4 exactly.
// ---------------------------------------------------------------------------
__global__ void combine_kernel() {
    const int b = blockIdx.y;
    const int d4 = threadIdx.x;  // 256 threads == DIM4
    const int nb = g_nb[b];
    const int nc = (nb + CHUNK - 1) / CHUNK;

    const float4* Eb = g_E4 + (size_t)(b * NCHUNK) * DIM4 + d4;
    const float*  Pb = g_Pc + b * NCHUNK;
    float4*       Sb = g_S4 + (size_t)(b * NCHUNK) * DIM4 + d4;

    float4 s = make_float4(0.f, 0.f, 0.f, 0.f);
    const int G = 16;
    float4 Ebuf[G];
    float  Pbuf[G];
    #pragma unroll
    for (int j = 0; j < G; j++) {
        Ebuf[j] = (j < nc) ? Eb[(size_t)j * DIM4] : make_float4(0.f, 0.f, 0.f, 0.f);
        Pbuf[j] = (j < nc) ? Pb[j] : 1.f;
    }
    for (int g = 0; g < NCHUNK && g < nc; g += G) {
        float4 En[G];
        float  Pn[G];
        #pragma unroll
        for (int j = 0; j < G; j++) {
            const int cc = g + G + j;
            En[j] = (cc < nc) ? Eb[(size_t)cc * DIM4] : make_float4(0.f, 0.f, 0.f, 0.f);
            Pn[j] = (cc < nc) ? Pb[cc] : 1.f;
        }
        #pragma unroll
        for (int j = 0; j < G; j++) {
            const int cc = g + j;
            if (cc < nc) {
                Sb[(size_t)cc * DIM4] = s;
                const float P = Pbuf[j];
                s.x = fmaf(P, s.x, Ebuf[j].x);
                s.y = fmaf(P, s.y, Ebuf[j].y);
                s.z = fmaf(P, s.z, Ebuf[j].z);
                s.w = fmaf(P, s.w, Ebuf[j].w);
            }
        }
        #pragma unroll
        for (int j = 0; j < G; j++) { Ebuf[j] = En[j]; Pbuf[j] = Pn[j]; }
    }
}

// ---------------------------------------------------------------------------
// Kernel 4: fused seeded re-scan + run-expansion to out (float4).
// grid (2, NCHUNK, BSZ), 128 threads.
// ---------------------------------------------------------------------------
__global__ void fused_out_kernel(const float* __restrict__ hidden,
                                 float* __restrict__ out) {
    const int b = blockIdx.z, c = blockIdx.y;
    const int d4 = blockIdx.x * 128 + threadIdx.x;
    const int nb = g_nb[b];
    const int k0 = c * CHUNK;
    if (k0 >= nb) return;
    const int n = min(CHUNK, nb - k0);

    __shared__ int   spos[CHUNK + 1];
    __shared__ float spk [CHUNK];
    if (threadIdx.x <= n) {
        const int kk = k0 + threadIdx.x;
        spos[threadIdx.x] = (kk < nb) ? g_pos[b * SEQ + kk] : SEQ;
    }
    if (threadIdx.x < n)
        spk[threadIdx.x] = g_pk[b * SEQ + k0 + threadIdx.x];
    __syncthreads();

    const float4* hb = (const float4*)hidden + (size_t)b * SEQ * DIM4 + d4;
    float4* ob = (float4*)out + (size_t)b * SEQ * DIM4 + d4;

    float4 s = g_S4[(size_t)(b * NCHUNK + c) * DIM4 + d4];

    #pragma unroll
    for (int j0 = 0; j0 < CHUNK; j0 += 8) {
        float4 h[8];
        #pragma unroll
        for (int jj = 0; jj < 8; jj++) {
            const int j = j0 + jj;
            h[jj] = (j < n) ? __ldg(hb + (size_t)spos[j] * DIM4)
                            : make_float4(0.f, 0.f, 0.f, 0.f);
        }
        #pragma unroll
        for (int jj = 0; jj < 8; jj++) {
            const int j = j0 + jj;
            if (j < n) {
                const float p = spk[j], a = 1.f - p;
                s.x = fmaf(a, s.x, p * h[jj].x);
                s.y = fmaf(a, s.y, p * h[jj].y);
                s.z = fmaf(a, s.z, p * h[jj].z);
                s.w = fmaf(a, s.w, p * h[jj].w);
                const int start = (k0 + j == 0) ? 0 : spos[j];
                const int end = spos[j + 1];
                for (int l = start; l < end; l++)
                    ob[(size_t)l * DIM4] = s;
            }
        }
    }
}

// ---------------------------------------------------------------------------
extern "C" void kernel_launch(void* const* d_in, const int* in_sizes, int n_in,
                              void* d_out, int out_size) {
    const float* hidden = (const float*)d_in[0];
    const float* prob   = (const float*)d_in[1];
    const void*  mask   = d_in[2];
    float* out = (float*)d_out;

    prep_kernel<<<BSZ, 1024>>>(prob, mask);
    escan_kernel<<<dim3(2, NCHUNK, BSZ), 128>>>(hidden);
    combine_kernel<<<dim3(1, BSZ), 256>>>();
    fused_out_kernel<<<dim3(2, NCHUNK, BSZ), 128>>>(hidden, out);
}